// round 2
// baseline (speedup 1.0000x reference)
#include <cuda_runtime.h>
#include <math.h>

#define S_LEN 2048
#define D_DIM 2048
#define NH    8
#define DH    256
#define TS    68      // transposed Q/K smem row stride (floats)
#define PS    68      // P smem row stride
#define NQT   32

// ---------------- device scratch (no allocation allowed) ----------------
__device__ float g_ipre[NH * S_LEN];
__device__ float g_fpre[NH * S_LEN];
__device__ float g_a [NH * S_LEN];   // a[s] = i_pre[s] - c[s]
__device__ float g_M [NH * S_LEN];   // prefix max of a
__device__ float g_en[NH * S_LEN];   // exp(-m[t])

// =========================================================================
// Gates: [2048 x 6144] @ [6144 x 16] -> i_pre, f_pre (pre-bias)
// grid: 128 blocks x 256 threads, 16 s-rows per block
// =========================================================================
__global__ __launch_bounds__(256)
void gates_kernel(const float* __restrict__ q, const float* __restrict__ k,
                  const float* __restrict__ v,
                  const float* __restrict__ Wi, const float* __restrict__ Wf) {
    __shared__ float Xs[16 * 260];
    __shared__ float Ws[256 * 20];
    __shared__ float red[4][64];
    const int tid = threadIdx.x;
    const int blk = blockIdx.x;          // rows blk*16 .. blk*16+15
    const int jsl = tid & 63;
    const int sg  = tid >> 6;            // 0..3 -> s rows sg*4..sg*4+3

    float acc[4][16];
    #pragma unroll
    for (int a = 0; a < 4; a++)
        #pragma unroll
        for (int g = 0; g < 16; g++) acc[a][g] = 0.f;

    for (int ch = 0; ch < 24; ch++) {
        __syncthreads();
        // weights chunk: rows ch*256 .. +255, 16 outputs (8 igate, 8 fgate)
        {
            const int jg = ch * 256 + tid;
            float4 w0 = *(const float4*)&Wi[jg * 8 + 0];
            float4 w1 = *(const float4*)&Wi[jg * 8 + 4];
            float4 w2 = *(const float4*)&Wf[jg * 8 + 0];
            float4 w3 = *(const float4*)&Wf[jg * 8 + 4];
            *(float4*)&Ws[tid * 20 + 0]  = w0;
            *(float4*)&Ws[tid * 20 + 4]  = w1;
            *(float4*)&Ws[tid * 20 + 8]  = w2;
            *(float4*)&Ws[tid * 20 + 12] = w3;
        }
        // X chunk: 16 rows x 256 features (chunk entirely inside q, k, or v)
        {
            const float* src = (ch < 8) ? q : (ch < 16) ? k : v;
            const int coff = (ch & 7) * 256;
            #pragma unroll
            for (int n = 0; n < 4; n++) {
                int idx = tid + n * 256;
                int row = idx >> 6, j4 = idx & 63;
                *(float4*)&Xs[row * 260 + j4 * 4] =
                    *(const float4*)&src[(blk * 16 + row) * D_DIM + coff + j4 * 4];
            }
        }
        __syncthreads();
        #pragma unroll
        for (int jj = 0; jj < 4; jj++) {
            const int j = jj * 64 + jsl;
            float4 w0 = *(const float4*)&Ws[j * 20 + 0];
            float4 w1 = *(const float4*)&Ws[j * 20 + 4];
            float4 w2 = *(const float4*)&Ws[j * 20 + 8];
            float4 w3 = *(const float4*)&Ws[j * 20 + 12];
            float wv[16] = {w0.x,w0.y,w0.z,w0.w, w1.x,w1.y,w1.z,w1.w,
                            w2.x,w2.y,w2.z,w2.w, w3.x,w3.y,w3.z,w3.w};
            #pragma unroll
            for (int cs = 0; cs < 4; cs++) {
                float x = Xs[(sg * 4 + cs) * 260 + j];
                #pragma unroll
                for (int g = 0; g < 16; g++) acc[cs][g] = fmaf(x, wv[g], acc[cs][g]);
            }
        }
    }
    // reduce over 64 j-slices: butterfly within warp, then 2 warps via smem
    #pragma unroll
    for (int cs = 0; cs < 4; cs++)
        #pragma unroll
        for (int g = 0; g < 16; g++)
            #pragma unroll
            for (int m = 16; m >= 1; m >>= 1)
                acc[cs][g] += __shfl_xor_sync(0xffffffffu, acc[cs][g], m);
    const int lane = tid & 31;
    const int halfw = (tid >> 5) & 1;
    if (halfw == 1 && lane == 0) {
        #pragma unroll
        for (int cs = 0; cs < 4; cs++)
            #pragma unroll
            for (int g = 0; g < 16; g++) red[sg][cs * 16 + g] = acc[cs][g];
    }
    __syncthreads();
    if (halfw == 0 && lane == 0) {
        #pragma unroll
        for (int cs = 0; cs < 4; cs++) {
            const int s = blk * 16 + sg * 4 + cs;
            #pragma unroll
            for (int g = 0; g < 16; g++) {
                float fv = acc[cs][g] + red[sg][cs * 16 + g];
                if (g < 8) g_ipre[g * S_LEN + s] = fv;
                else       g_fpre[(g - 8) * S_LEN + s] = fv;
            }
        }
    }
}

// =========================================================================
// Scan: per head, c = cumsum(logsigmoid(f)), a = i - c, M = prefmax(a),
//       en = exp(-(c+M)).  1 block, 8 warps (1 per head).
// =========================================================================
__global__ __launch_bounds__(256)
void scan_kernel(const float* __restrict__ ibias, const float* __restrict__ fbias) {
    const int w = threadIdx.x >> 5;
    const int lane = threadIdx.x & 31;
    const float ib = ibias[w], fb = fbias[w];
    float cc = 0.f, cM = -3.4e38f;
    for (int i0 = 0; i0 < S_LEN; i0 += 32) {
        const int s = i0 + lane;
        float f = g_fpre[w * S_LEN + s] + fb;
        float lf = fminf(f, 0.f) - log1pf(expf(-fabsf(f)));
        #pragma unroll
        for (int o = 1; o < 32; o <<= 1) {
            float t = __shfl_up_sync(0xffffffffu, lf, o);
            if (lane >= o) lf += t;
        }
        float c = cc + lf;
        float a = g_ipre[w * S_LEN + s] + ib - c;
        float mx = a;
        #pragma unroll
        for (int o = 1; o < 32; o <<= 1) {
            float t = __shfl_up_sync(0xffffffffu, mx, o);
            if (lane >= o) mx = fmaxf(mx, t);
        }
        float M = fmaxf(cM, mx);
        g_a[w * S_LEN + s]  = a;
        g_M[w * S_LEN + s]  = M;
        g_en[w * S_LEN + s] = expf(-(c + M));
        cc = __shfl_sync(0xffffffffu, c, 31);
        cM = __shfl_sync(0xffffffffu, M, 31);
    }
}

// =========================================================================
// Main: per (qtile, head) block. 64 queries x 256 dims, fp32 flash-style.
// =========================================================================
__global__ __launch_bounds__(256, 1)
void attn_kernel(const float* __restrict__ q, const float* __restrict__ k,
                 const float* __restrict__ v, const float* __restrict__ ow,
                 float* __restrict__ out) {
    extern __shared__ float sm[];
    float* Qs  = sm;                         // 256*68
    float* Ks  = Qs + 256 * TS;              // 256*68
    float* Vs  = Ks + 256 * TS;              // 64*256
    float* Ps  = Vs + 64 * 256;              // 64*68
    float* ash = Ps + 64 * PS;               // 64

    const int qt  = (NQT - 1) - blockIdx.x;  // heavy blocks first
    const int h   = blockIdx.y;
    const int tid = threadIdx.x;
    const int lane = tid & 31;
    const int wrp  = tid >> 5;
    const int jx = tid & 15;                 // 0..15 (s / d columns)
    const int ix = tid >> 4;                 // 0..15 (t rows)

    const float* qh = q + h * DH;
    const float* kh = k + h * DH;
    const float* vh = v + h * DH;

    // --- load Q transposed: Qs[d*TS + t_local] ---
    {
        const int t0 = qt * 64;
        for (int r4 = wrp; r4 < 16; r4 += 8) {
            #pragma unroll
            for (int dc = 0; dc < 8; dc++) {
                const int d = dc * 32 + lane;
                float4 vq;
                vq.x = qh[(t0 + r4 * 4 + 0) * D_DIM + d];
                vq.y = qh[(t0 + r4 * 4 + 1) * D_DIM + d];
                vq.z = qh[(t0 + r4 * 4 + 2) * D_DIM + d];
                vq.w = qh[(t0 + r4 * 4 + 3) * D_DIM + d];
                *(float4*)&Qs[d * TS + r4 * 4] = vq;
            }
        }
    }
    float Mreg[4];
    #pragma unroll
    for (int c = 0; c < 4; c++) Mreg[c] = g_M[h * S_LEN + qt * 64 + ix * 4 + c];

    float4 acc[4][4];                        // [t-row][c], d = c*64 + jx*4 + comp
    #pragma unroll
    for (int a = 0; a < 4; a++)
        #pragma unroll
        for (int b = 0; b < 4; b++) acc[a][b] = make_float4(0.f, 0.f, 0.f, 0.f);
    float rs[4] = {0.f, 0.f, 0.f, 0.f};

    for (int kt = 0; kt <= qt; kt++) {
        __syncthreads();
        const int s0 = kt * 64;
        // K transposed
        for (int r4 = wrp; r4 < 16; r4 += 8) {
            #pragma unroll
            for (int dc = 0; dc < 8; dc++) {
                const int d = dc * 32 + lane;
                float4 vk;
                vk.x = kh[(s0 + r4 * 4 + 0) * D_DIM + d];
                vk.y = kh[(s0 + r4 * 4 + 1) * D_DIM + d];
                vk.z = kh[(s0 + r4 * 4 + 2) * D_DIM + d];
                vk.w = kh[(s0 + r4 * 4 + 3) * D_DIM + d];
                *(float4*)&Ks[d * TS + r4 * 4] = vk;
            }
        }
        // V natural
        #pragma unroll
        for (int n = 0; n < 16; n++) {
            int idx = tid + n * 256;
            int sv = idx >> 6, dq = idx & 63;
            *(float4*)&Vs[sv * 256 + dq * 4] =
                *(const float4*)&vh[(s0 + sv) * D_DIM + dq * 4];
        }
        if (tid < 64) ash[tid] = g_a[h * S_LEN + s0 + tid];
        __syncthreads();

        // ---- stage A: P = (Q K^T)/16 * exp(a[s]-M[t]), causal mask ----
        float pa[4][4];
        #pragma unroll
        for (int a = 0; a < 4; a++)
            #pragma unroll
            for (int b = 0; b < 4; b++) pa[a][b] = 0.f;
        const float* aptr = Qs + ix * 4;
        const float* bptr = Ks + jx * 4;
        #pragma unroll 4
        for (int d = 0; d < 256; d++) {
            float4 A = *(const float4*)(aptr + d * TS);
            float4 B = *(const float4*)(bptr + d * TS);
            float aa[4] = {A.x, A.y, A.z, A.w};
            float bb[4] = {B.x, B.y, B.z, B.w};
            #pragma unroll
            for (int ct = 0; ct < 4; ct++)
                #pragma unroll
                for (int cs = 0; cs < 4; cs++)
                    pa[ct][cs] = fmaf(aa[ct], bb[cs], pa[ct][cs]);
        }
        float aw[4];
        #pragma unroll
        for (int cs = 0; cs < 4; cs++) aw[cs] = ash[jx * 4 + cs];
        #pragma unroll
        for (int ct = 0; ct < 4; ct++) {
            const int tg = qt * 64 + ix * 4 + ct;
            float4 pv;
            float* pp = (float*)&pv;
            #pragma unroll
            for (int cs = 0; cs < 4; cs++) {
                const int sg = s0 + jx * 4 + cs;
                float cv = pa[ct][cs] * 0.0625f * __expf(aw[cs] - Mreg[ct]);
                if (sg > tg) cv = 0.f;
                pp[cs] = cv;
            }
            *(float4*)&Ps[(ix * 4 + ct) * PS + jx * 4] = pv;
        }
        __syncthreads();

        // ---- stage B: acc += P @ V, rowsum ----
        #pragma unroll 2
        for (int s = 0; s < 64; s++) {
            float pp[4];
            #pragma unroll
            for (int ct = 0; ct < 4; ct++) {
                pp[ct] = Ps[(ix * 4 + ct) * PS + s];
                rs[ct] += pp[ct];
            }
            #pragma unroll
            for (int c = 0; c < 4; c++) {
                float4 vv = *(const float4*)(Vs + s * 256 + c * 64 + jx * 4);
                #pragma unroll
                for (int ct = 0; ct < 4; ct++) {
                    acc[ct][c].x = fmaf(pp[ct], vv.x, acc[ct][c].x);
                    acc[ct][c].y = fmaf(pp[ct], vv.y, acc[ct][c].y);
                    acc[ct][c].z = fmaf(pp[ct], vv.z, acc[ct][c].z);
                    acc[ct][c].w = fmaf(pp[ct], vv.w, acc[ct][c].w);
                }
            }
        }
    }

    // ---- epilogue: normalize + per-head LayerNorm ----
    float4 wv[4];
    #pragma unroll
    for (int c = 0; c < 4; c++)
        wv[c] = *(const float4*)(ow + h * DH + c * 64 + jx * 4);
    #pragma unroll
    for (int ct = 0; ct < 4; ct++) {
        const int tg = qt * 64 + ix * 4 + ct;
        float e = g_en[h * S_LEN + tg];
        float nn = fmaxf(fabsf(rs[ct]), e);
        float inv = 1.f / (nn + 1e-6f);
        float hv[16];
        float sum = 0.f, sq = 0.f;
        #pragma unroll
        for (int c = 0; c < 4; c++) {
            hv[c * 4 + 0] = acc[ct][c].x * inv;
            hv[c * 4 + 1] = acc[ct][c].y * inv;
            hv[c * 4 + 2] = acc[ct][c].z * inv;
            hv[c * 4 + 3] = acc[ct][c].w * inv;
            #pragma unroll
            for (int kk = 0; kk < 4; kk++) {
                sum += hv[c * 4 + kk];
                sq  += hv[c * 4 + kk] * hv[c * 4 + kk];
            }
        }
        #pragma unroll
        for (int m = 1; m <= 8; m <<= 1) {
            sum += __shfl_xor_sync(0xffffffffu, sum, m);
            sq  += __shfl_xor_sync(0xffffffffu, sq,  m);
        }
        float mean = sum * (1.f / 256.f);
        float var  = sq * (1.f / 256.f) - mean * mean;
        float rstd = rsqrtf(var + 1e-6f);
        #pragma unroll
        for (int c = 0; c < 4; c++) {
            float4 o;
            o.x = (hv[c * 4 + 0] - mean) * rstd * wv[c].x;
            o.y = (hv[c * 4 + 1] - mean) * rstd * wv[c].y;
            o.z = (hv[c * 4 + 2] - mean) * rstd * wv[c].z;
            o.w = (hv[c * 4 + 3] - mean) * rstd * wv[c].w;
            *(float4*)(out + tg * D_DIM + h * DH + c * 64 + jx * 4) = o;
        }
    }
}

// =========================================================================
extern "C" void kernel_launch(void* const* d_in, const int* in_sizes, int n_in,
                              void* d_out, int out_size) {
    const float* q  = (const float*)d_in[0];
    const float* k  = (const float*)d_in[1];
    const float* v  = (const float*)d_in[2];
    const float* Wi = (const float*)d_in[3];
    const float* bi = (const float*)d_in[4];
    const float* Wf = (const float*)d_in[5];
    const float* bf = (const float*)d_in[6];
    const float* ow = (const float*)d_in[7];
    float* out = (float*)d_out;

    const int smem = (256 * TS * 2 + 64 * 256 + 64 * PS + 64) * (int)sizeof(float);
    cudaFuncSetAttribute(attn_kernel, cudaFuncAttributeMaxDynamicSharedMemorySize, smem);

    gates_kernel<<<128, 256>>>(q, k, v, Wi, Wf);
    scan_kernel<<<1, 256>>>(bi, bf);
    attn_kernel<<<dim3(NQT, NH), 256, smem>>>(q, k, v, ow, out);
}

// round 3
// speedup vs baseline: 1.1682x; 1.1682x over previous
#include <cuda_runtime.h>
#include <math.h>

#define S_LEN 2048
#define D_DIM 2048
#define NH    8
#define DH    256
#define ST2   66      // Q/K smem row stride in float2 units ([dpair][t] layout)
#define PS    68      // P smem row stride (floats)
#define NQT   32

// ---------------- device scratch (no allocation allowed) ----------------
__device__ float g_part[S_LEN * 16 * 8];   // gate partials [(s*16+g)*8 + kpart]
__device__ float g_a [NH * S_LEN];         // a[s] = i_pre[s] - c[s]
__device__ float g_M [NH * S_LEN];         // prefix max of a
__device__ float g_en[NH * S_LEN];         // exp(-m[t])

// ---------------- f32x2 packed-FMA helpers ----------------
__device__ __forceinline__ unsigned long long pack2(float x, float y) {
    unsigned long long r;
    asm("mov.b64 %0,{%1,%2};" : "=l"(r) : "f"(x), "f"(y));
    return r;
}
__device__ __forceinline__ void fma2(unsigned long long& d,
                                     unsigned long long a, unsigned long long b) {
    asm("fma.rn.f32x2 %0,%1,%2,%0;" : "+l"(d) : "l"(a), "l"(b));
}
__device__ __forceinline__ float2 unpack2(unsigned long long v) {
    float2 r;
    asm("mov.b64 {%0,%1},%2;" : "=f"(r.x), "=f"(r.y) : "l"(v));
    return r;
}

// =========================================================================
// Gates split-K: grid (128 s-tiles x 8 k-parts), 16 rows x 768 features each.
// Writes 16-gate partials; reduced (fixed order) inside scan_kernel.
// =========================================================================
__global__ __launch_bounds__(256)
void gates_kernel(const float* __restrict__ q, const float* __restrict__ k,
                  const float* __restrict__ v,
                  const float* __restrict__ Wi, const float* __restrict__ Wf) {
    __shared__ float Xs[16 * 260];
    __shared__ float Ws[256 * 20];
    __shared__ float red[4][64];
    const int tid = threadIdx.x;
    const int blk = blockIdx.x;          // rows blk*16 .. +15
    const int kp  = blockIdx.y;          // feature part kp*768 .. +767
    const int jsl = tid & 63;
    const int sg  = tid >> 6;            // 0..3 -> rows sg*4..sg*4+3

    float acc[4][16];
    #pragma unroll
    for (int a = 0; a < 4; a++)
        #pragma unroll
        for (int g = 0; g < 16; g++) acc[a][g] = 0.f;

    for (int ch = 0; ch < 3; ch++) {
        const int rbase = kp * 768 + ch * 256;
        __syncthreads();
        {   // weights chunk: rows rbase..+255, 16 outputs
            const int jg = rbase + tid;
            float4 w0 = *(const float4*)&Wi[jg * 8 + 0];
            float4 w1 = *(const float4*)&Wi[jg * 8 + 4];
            float4 w2 = *(const float4*)&Wf[jg * 8 + 0];
            float4 w3 = *(const float4*)&Wf[jg * 8 + 4];
            *(float4*)&Ws[tid * 20 + 0]  = w0;
            *(float4*)&Ws[tid * 20 + 4]  = w1;
            *(float4*)&Ws[tid * 20 + 8]  = w2;
            *(float4*)&Ws[tid * 20 + 12] = w3;
        }
        {   // X chunk: 16 rows x 256 features (chunk entirely inside one tensor)
            const int tsel = rbase >> 11;
            const float* src = (tsel == 0) ? q : (tsel == 1) ? k : v;
            const int coff = rbase & 2047;
            #pragma unroll
            for (int n = 0; n < 4; n++) {
                int idx = tid + n * 256;
                int row = idx >> 6, j4 = idx & 63;
                *(float4*)&Xs[row * 260 + j4 * 4] =
                    *(const float4*)&src[(blk * 16 + row) * D_DIM + coff + j4 * 4];
            }
        }
        __syncthreads();
        #pragma unroll
        for (int jj = 0; jj < 4; jj++) {
            const int j = jj * 64 + jsl;
            float4 w0 = *(const float4*)&Ws[j * 20 + 0];
            float4 w1 = *(const float4*)&Ws[j * 20 + 4];
            float4 w2 = *(const float4*)&Ws[j * 20 + 8];
            float4 w3 = *(const float4*)&Ws[j * 20 + 12];
            float wv[16] = {w0.x,w0.y,w0.z,w0.w, w1.x,w1.y,w1.z,w1.w,
                            w2.x,w2.y,w2.z,w2.w, w3.x,w3.y,w3.z,w3.w};
            #pragma unroll
            for (int cs = 0; cs < 4; cs++) {
                float x = Xs[(sg * 4 + cs) * 260 + j];
                #pragma unroll
                for (int g = 0; g < 16; g++) acc[cs][g] = fmaf(x, wv[g], acc[cs][g]);
            }
        }
    }
    // reduce over 64 j-slices: warp butterfly + 2-warp combine
    #pragma unroll
    for (int cs = 0; cs < 4; cs++)
        #pragma unroll
        for (int g = 0; g < 16; g++)
            #pragma unroll
            for (int m = 16; m >= 1; m >>= 1)
                acc[cs][g] += __shfl_xor_sync(0xffffffffu, acc[cs][g], m);
    const int lane = tid & 31;
    const int halfw = (tid >> 5) & 1;
    if (halfw == 1 && lane == 0) {
        #pragma unroll
        for (int cs = 0; cs < 4; cs++)
            #pragma unroll
            for (int g = 0; g < 16; g++) red[sg][cs * 16 + g] = acc[cs][g];
    }
    __syncthreads();
    if (halfw == 0 && lane == 0) {
        #pragma unroll
        for (int cs = 0; cs < 4; cs++) {
            const int s = blk * 16 + sg * 4 + cs;
            #pragma unroll
            for (int g = 0; g < 16; g++)
                g_part[(s * 16 + g) * 8 + kp] = acc[cs][g] + red[sg][cs * 16 + g];
        }
    }
}

// =========================================================================
// Scan: reduce split-K partials, then per-head prefix:
//   c=cumsum(logsigmoid(f)), a=i-c, M=prefmax(a), en=exp(-(c+M))
// 1 block, 8 warps (one per head).
// =========================================================================
__global__ __launch_bounds__(256)
void scan_kernel(const float* __restrict__ ibias, const float* __restrict__ fbias) {
    const int w = threadIdx.x >> 5;
    const int lane = threadIdx.x & 31;
    const float ib = ibias[w], fb = fbias[w];
    float cc = 0.f, cM = -3.4e38f;
    for (int i0 = 0; i0 < S_LEN; i0 += 32) {
        const int s = i0 + lane;
        float4 fi0 = *(const float4*)&g_part[(s * 16 + w) * 8];
        float4 fi1 = *(const float4*)&g_part[(s * 16 + w) * 8 + 4];
        float4 ff0 = *(const float4*)&g_part[(s * 16 + 8 + w) * 8];
        float4 ff1 = *(const float4*)&g_part[(s * 16 + 8 + w) * 8 + 4];
        float ip = ((fi0.x + fi0.y) + (fi0.z + fi0.w)) +
                   ((fi1.x + fi1.y) + (fi1.z + fi1.w)) + ib;
        float f  = ((ff0.x + ff0.y) + (ff0.z + ff0.w)) +
                   ((ff1.x + ff1.y) + (ff1.z + ff1.w)) + fb;
        float lf = fminf(f, 0.f) - log1pf(expf(-fabsf(f)));
        #pragma unroll
        for (int o = 1; o < 32; o <<= 1) {
            float t = __shfl_up_sync(0xffffffffu, lf, o);
            if (lane >= o) lf += t;
        }
        float c = cc + lf;
        float a = ip - c;
        float mx = a;
        #pragma unroll
        for (int o = 1; o < 32; o <<= 1) {
            float t = __shfl_up_sync(0xffffffffu, mx, o);
            if (lane >= o) mx = fmaxf(mx, t);
        }
        float M = fmaxf(cM, mx);
        g_a[w * S_LEN + s]  = a;
        g_M[w * S_LEN + s]  = M;
        g_en[w * S_LEN + s] = expf(-(c + M));
        cc = __shfl_sync(0xffffffffu, c, 31);
        cM = __shfl_sync(0xffffffffu, M, 31);
    }
}

// =========================================================================
// Main: grid (16, 8). Block bx processes qt = 31-bx then qt = bx
// (33 tile-units each -> perfect balance, single wave on 148 SMs).
// Q/K staged as [dpair][t] float2 tiles -> packed f32x2 FMA, no splats.
// =========================================================================
__global__ __launch_bounds__(256, 1)
void attn_kernel(const float* __restrict__ q, const float* __restrict__ k,
                 const float* __restrict__ v, const float* __restrict__ ow,
                 float* __restrict__ out) {
    extern __shared__ float sm[];
    float2* Qs2 = (float2*)sm;                       // 128 * 66 float2
    float2* Ks2 = Qs2 + 128 * ST2;                   // 128 * 66 float2
    float*  Vs  = (float*)(Ks2 + 128 * ST2);         // 64 * 256 floats
    float*  Ps  = Vs + 64 * 256;                     // 64 * 68
    float*  ash = Ps + 64 * PS;                      // 64

    const int bx  = blockIdx.x;
    const int h   = blockIdx.y;
    const int tid = threadIdx.x;
    const int lane = tid & 31;
    const int wrp  = tid >> 5;
    const int jx = tid & 15;                         // s / d column group
    const int ix = tid >> 4;                         // t row group

    const float* qh = q + h * DH;
    const float* kh = k + h * DH;
    const float* vh = v + h * DH;

    float4 wv[4];
    #pragma unroll
    for (int c = 0; c < 4; c++)
        wv[c] = *(const float4*)(ow + h * DH + c * 64 + jx * 4);

    for (int pass = 0; pass < 2; pass++) {
        const int qt = pass ? bx : (NQT - 1 - bx);
        const int t0 = qt * 64;

        // --- stage Q: Qs2[dp][t] = (Q[t,2dp], Q[t,2dp+1]) ---
        for (int r4 = wrp; r4 < 16; r4 += 8) {
            #pragma unroll
            for (int dc = 0; dc < 4; dc++) {
                const int dp = dc * 32 + lane;
                float2 x0 = *(const float2*)&qh[(t0 + r4 * 4 + 0) * D_DIM + dp * 2];
                float2 x1 = *(const float2*)&qh[(t0 + r4 * 4 + 1) * D_DIM + dp * 2];
                float2 x2 = *(const float2*)&qh[(t0 + r4 * 4 + 2) * D_DIM + dp * 2];
                float2 x3 = *(const float2*)&qh[(t0 + r4 * 4 + 3) * D_DIM + dp * 2];
                *(float4*)(Qs2 + dp * ST2 + r4 * 4)     = make_float4(x0.x, x0.y, x1.x, x1.y);
                *(float4*)(Qs2 + dp * ST2 + r4 * 4 + 2) = make_float4(x2.x, x2.y, x3.x, x3.y);
            }
        }
        float Mreg[4];
        #pragma unroll
        for (int c = 0; c < 4; c++) Mreg[c] = g_M[h * S_LEN + t0 + ix * 4 + c];

        unsigned long long acc2[4][8];               // [ct][c*2+half], d = c*64+jx*4
        #pragma unroll
        for (int a = 0; a < 4; a++)
            #pragma unroll
            for (int b = 0; b < 8; b++) acc2[a][b] = 0ull;
        float rs[4] = {0.f, 0.f, 0.f, 0.f};

        for (int kt = 0; kt <= qt; kt++) {
            __syncthreads();
            const int s0 = kt * 64;
            // K tile: Ks2[dp][s]
            for (int r4 = wrp; r4 < 16; r4 += 8) {
                #pragma unroll
                for (int dc = 0; dc < 4; dc++) {
                    const int dp = dc * 32 + lane;
                    float2 x0 = *(const float2*)&kh[(s0 + r4 * 4 + 0) * D_DIM + dp * 2];
                    float2 x1 = *(const float2*)&kh[(s0 + r4 * 4 + 1) * D_DIM + dp * 2];
                    float2 x2 = *(const float2*)&kh[(s0 + r4 * 4 + 2) * D_DIM + dp * 2];
                    float2 x3 = *(const float2*)&kh[(s0 + r4 * 4 + 3) * D_DIM + dp * 2];
                    *(float4*)(Ks2 + dp * ST2 + r4 * 4)     = make_float4(x0.x, x0.y, x1.x, x1.y);
                    *(float4*)(Ks2 + dp * ST2 + r4 * 4 + 2) = make_float4(x2.x, x2.y, x3.x, x3.y);
                }
            }
            // V tile, natural layout
            #pragma unroll
            for (int n = 0; n < 16; n++) {
                int idx = tid + n * 256;
                int sv = idx >> 6, dq = idx & 63;
                *(float4*)&Vs[sv * 256 + dq * 4] =
                    *(const float4*)&vh[(s0 + sv) * D_DIM + dq * 4];
            }
            if (tid < 64) ash[tid] = g_a[h * S_LEN + s0 + tid];
            __syncthreads();

            // ---- stage A: packed over d-pairs, horizontal add at end ----
            unsigned long long pa2[4][4];
            #pragma unroll
            for (int a = 0; a < 4; a++)
                #pragma unroll
                for (int b = 0; b < 4; b++) pa2[a][b] = 0ull;
            const float2* Abase = Qs2 + ix * 4;
            const float2* Bbase = Ks2 + jx * 4;
            #pragma unroll 2
            for (int dp = 0; dp < 128; dp++) {
                ulonglong2 aL = *(const ulonglong2*)(Abase + dp * ST2);
                ulonglong2 aH = *(const ulonglong2*)(Abase + dp * ST2 + 2);
                ulonglong2 bL = *(const ulonglong2*)(Bbase + dp * ST2);
                ulonglong2 bH = *(const ulonglong2*)(Bbase + dp * ST2 + 2);
                unsigned long long av[4] = {aL.x, aL.y, aH.x, aH.y};
                unsigned long long bv[4] = {bL.x, bL.y, bH.x, bH.y};
                #pragma unroll
                for (int ct = 0; ct < 4; ct++)
                    #pragma unroll
                    for (int cs = 0; cs < 4; cs++)
                        fma2(pa2[ct][cs], av[ct], bv[cs]);
            }
            float aw[4];
            #pragma unroll
            for (int cs = 0; cs < 4; cs++) aw[cs] = ash[jx * 4 + cs];
            #pragma unroll
            for (int ct = 0; ct < 4; ct++) {
                const int tg = t0 + ix * 4 + ct;
                float4 pv;
                float* pp = (float*)&pv;
                #pragma unroll
                for (int cs = 0; cs < 4; cs++) {
                    float2 hh = unpack2(pa2[ct][cs]);
                    const int sg = s0 + jx * 4 + cs;
                    float cv = (hh.x + hh.y) * 0.0625f * __expf(aw[cs] - Mreg[ct]);
                    if (sg > tg) cv = 0.f;
                    pp[cs] = cv;
                }
                *(float4*)&Ps[(ix * 4 + ct) * PS + jx * 4] = pv;
            }
            __syncthreads();

            // ---- stage B: acc += P @ V (packed over adjacent d), rowsum ----
            #pragma unroll 2
            for (int s = 0; s < 64; s++) {
                float ppv[4];
                unsigned long long pp2[4];
                #pragma unroll
                for (int ct = 0; ct < 4; ct++) {
                    ppv[ct] = Ps[(ix * 4 + ct) * PS + s];
                    rs[ct] += ppv[ct];
                    pp2[ct] = pack2(ppv[ct], ppv[ct]);
                }
                #pragma unroll
                for (int c = 0; c < 4; c++) {
                    ulonglong2 vvp = *(const ulonglong2*)(Vs + s * 256 + c * 64 + jx * 4);
                    #pragma unroll
                    for (int ct = 0; ct < 4; ct++) {
                        fma2(acc2[ct][c * 2 + 0], pp2[ct], vvp.x);
                        fma2(acc2[ct][c * 2 + 1], pp2[ct], vvp.y);
                    }
                }
            }
        }

        // ---- epilogue: normalize + per-head LayerNorm ----
        #pragma unroll
        for (int ct = 0; ct < 4; ct++) {
            const int tg = t0 + ix * 4 + ct;
            float e = g_en[h * S_LEN + tg];
            float nn = fmaxf(fabsf(rs[ct]), e);
            float inv = 1.f / (nn + 1e-6f);
            float hv[16];
            float sum = 0.f, sq = 0.f;
            #pragma unroll
            for (int c = 0; c < 4; c++) {
                float2 lo = unpack2(acc2[ct][c * 2 + 0]);
                float2 hi = unpack2(acc2[ct][c * 2 + 1]);
                hv[c * 4 + 0] = lo.x * inv;
                hv[c * 4 + 1] = lo.y * inv;
                hv[c * 4 + 2] = hi.x * inv;
                hv[c * 4 + 3] = hi.y * inv;
                #pragma unroll
                for (int kk = 0; kk < 4; kk++) {
                    sum += hv[c * 4 + kk];
                    sq  += hv[c * 4 + kk] * hv[c * 4 + kk];
                }
            }
            #pragma unroll
            for (int m = 1; m <= 8; m <<= 1) {
                sum += __shfl_xor_sync(0xffffffffu, sum, m);
                sq  += __shfl_xor_sync(0xffffffffu, sq,  m);
            }
            float mean = sum * (1.f / 256.f);
            float var  = sq * (1.f / 256.f) - mean * mean;
            float rstd = rsqrtf(var + 1e-6f);
            #pragma unroll
            for (int c = 0; c < 4; c++) {
                float4 o;
                o.x = (hv[c * 4 + 0] - mean) * rstd * wv[c].x;
                o.y = (hv[c * 4 + 1] - mean) * rstd * wv[c].y;
                o.z = (hv[c * 4 + 2] - mean) * rstd * wv[c].z;
                o.w = (hv[c * 4 + 3] - mean) * rstd * wv[c].w;
                *(float4*)(out + tg * D_DIM + h * DH + c * 64 + jx * 4) = o;
            }
        }
        __syncthreads();   // protect smem before next pass overwrites
    }
}

// =========================================================================
extern "C" void kernel_launch(void* const* d_in, const int* in_sizes, int n_in,
                              void* d_out, int out_size) {
    const float* q  = (const float*)d_in[0];
    const float* k  = (const float*)d_in[1];
    const float* v  = (const float*)d_in[2];
    const float* Wi = (const float*)d_in[3];
    const float* bi = (const float*)d_in[4];
    const float* Wf = (const float*)d_in[5];
    const float* bf = (const float*)d_in[6];
    const float* ow = (const float*)d_in[7];
    float* out = (float*)d_out;

    const int smem = (128 * ST2 * 2) * (int)sizeof(float2) +
                     (64 * 256 + 64 * PS + 64) * (int)sizeof(float);
    cudaFuncSetAttribute(attn_kernel, cudaFuncAttributeMaxDynamicSharedMemorySize, smem);

    gates_kernel<<<dim3(128, 8), 256>>>(q, k, v, Wi, Wf);
    scan_kernel<<<1, 256>>>(bi, bf);
    attn_kernel<<<dim3(16, NH), 256, smem>>>(q, k, v, ow, out);
}